// round 7
// baseline (speedup 1.0000x reference)
#include <cuda_runtime.h>

#define D_MODEL 1024
#define SEQ     2048
#define BATCH   2
#define NH      16
#define DH      64
#define M_TOT   (BATCH * SEQ)   // 4096 rows

// Scratch (allocation-free rule: __device__ globals)
__device__ float g_qkv[(size_t)M_TOT * 3 * D_MODEL];   // [4096, 3072]
__device__ float g_attn[(size_t)M_TOT * D_MODEL];      // [4096, 1024]

// ---------------------------------------------------------------------------
// SGEMM with bias: C[M,N] = A[M,K] @ B[K,N] + bias[N]
// 64x64 tile, BK=16, 256 threads, 4x4 per-thread micro-tile, float4 I/O.
// As is transposed (+pad 68 to keep float4 alignment & kill bank conflicts).
// Requires M%64==0, N%64==0, K%16==0 (true for all shapes here).
// ---------------------------------------------------------------------------
__global__ __launch_bounds__(256) void sgemm_bias(
    const float* __restrict__ A, const float* __restrict__ B,
    const float* __restrict__ bias, float* __restrict__ C,
    int M, int N, int K)
{
    __shared__ float As[16][68];   // [kk][m]
    __shared__ float Bs[16][64];   // [kk][n]

    const int tid = threadIdx.x;
    const int tx = tid & 15;        // 0..15 -> n micro
    const int ty = tid >> 4;        // 0..15 -> m micro
    const int m0 = blockIdx.y * 64;
    const int n0 = blockIdx.x * 64;

    // load assignments
    const int arow = tid >> 2;          // 0..63 (m within tile)
    const int akk  = (tid & 3) * 4;     // 0,4,8,12 (k within tile)
    const int brow = tid >> 4;          // 0..15 (k within tile)
    const int bcol = (tid & 15) * 4;    // 0..60 (n within tile)

    const float* Aptr = A + (size_t)(m0 + arow) * K + akk;
    const float* Bptr = B + (size_t)brow * N + n0 + bcol;

    float acc[4][4] = {};

    for (int k0 = 0; k0 < K; k0 += 16) {
        float4 av = *(const float4*)(Aptr + k0);
        As[akk + 0][arow] = av.x;
        As[akk + 1][arow] = av.y;
        As[akk + 2][arow] = av.z;
        As[akk + 3][arow] = av.w;
        *(float4*)(&Bs[brow][bcol]) = *(const float4*)(Bptr + (size_t)k0 * N);
        __syncthreads();

        #pragma unroll
        for (int kk = 0; kk < 16; kk++) {
            float4 a4 = *(const float4*)(&As[kk][ty * 4]);
            float4 b4 = *(const float4*)(&Bs[kk][tx * 4]);
            float ar[4] = {a4.x, a4.y, a4.z, a4.w};
            float br[4] = {b4.x, b4.y, b4.z, b4.w};
            #pragma unroll
            for (int i = 0; i < 4; i++)
                #pragma unroll
                for (int j = 0; j < 4; j++)
                    acc[i][j] = fmaf(ar[i], br[j], acc[i][j]);
        }
        __syncthreads();
    }

    float4 bb = *(const float4*)(bias + n0 + tx * 4);
    #pragma unroll
    for (int i = 0; i < 4; i++) {
        float4 r;
        r.x = acc[i][0] + bb.x;
        r.y = acc[i][1] + bb.y;
        r.z = acc[i][2] + bb.z;
        r.w = acc[i][3] + bb.w;
        *(float4*)(C + (size_t)(m0 + ty * 4 + i) * N + n0 + tx * 4) = r;
    }
}

// ---------------------------------------------------------------------------
// Flash attention, fp32, Dh=64.
// Block = 64 queries of one (b,h). 256 threads as a 16x16 grid, 4x4 per-thread
// tiles for both S (64x64) and O (64 x Dh=64).
// Shared tiles (exactly 48 KB static):
//   Qt : transposed+swizzled Q  [d][r]   (loaded once)
//   Kt : transposed+swizzled K  [d][c]   (reused as transposed P [k][r])
//   Vs : natural V              [k][d]
// Swizzle: within row d, logical 4-float group g lives at group (g ^ ((d>>2)&15)).
// This makes every inner-loop LDS.128 conflict-free and all stores ~conflict-free
// while keeping row stride 64 (fits 48 KB static smem).
// ---------------------------------------------------------------------------
__device__ __forceinline__ int swzoff(int d, int g) {
    return d * 64 + (((g ^ ((d >> 2) & 15)) << 2));
}

__global__ __launch_bounds__(256) void attn_kernel(
    const float* __restrict__ qkv,   // [M_TOT, 3*D_MODEL]
    float* __restrict__ out)         // [M_TOT, D_MODEL]
{
    __shared__ float Qt[64 * 64];
    __shared__ float Kt[64 * 64];   // aliased as Pt after S is computed
    __shared__ float Vs[64 * 64];

    const int tid = threadIdx.x;
    const int tx = tid & 15;        // key / d micro index
    const int ty = tid >> 4;        // query-row micro index
    const int q0 = blockIdx.x * 64;
    const int h  = blockIdx.y;
    const int b  = blockIdx.z;
    const int bT = b * SEQ;
    const int hoff = h * DH;

    // ---- load Q tile (transposed + swizzled) ----
    #pragma unroll
    for (int it = 0; it < 4; it++) {
        int r  = (tid >> 4) + 16 * it;   // 0..63
        int ch = tid & 15;               // 4-float chunk along d
        float4 qv = *(const float4*)(qkv + (size_t)(bT + q0 + r) * (3 * D_MODEL) + hoff + ch * 4);
        float qa[4] = {qv.x, qv.y, qv.z, qv.w};
        #pragma unroll
        for (int i = 0; i < 4; i++) {
            int d = ch * 4 + i;
            Qt[swzoff(d, r >> 2) + (r & 3)] = qa[i];
        }
    }

    float m[4], l[4], o[4][4];
    #pragma unroll
    for (int i = 0; i < 4; i++) {
        m[i] = -1e30f;
        l[i] = 0.f;
        #pragma unroll
        for (int j = 0; j < 4; j++) o[i][j] = 0.f;
    }

    for (int kt = 0; kt < SEQ / 64; kt++) {
        const int k0 = kt * 64;
        __syncthreads();   // previous iteration's Pt/Vs reads done (also covers Qt stores on kt=0)

        // ---- load K (transposed+swizzled) and V (natural) tiles ----
        #pragma unroll
        for (int it = 0; it < 4; it++) {
            int r  = (tid >> 4) + 16 * it;
            int ch = tid & 15;
            const float* src = qkv + (size_t)(bT + k0 + r) * (3 * D_MODEL) + hoff;
            float4 kv = *(const float4*)(src + D_MODEL + ch * 4);
            float4 vv = *(const float4*)(src + 2 * D_MODEL + ch * 4);
            float ka[4] = {kv.x, kv.y, kv.z, kv.w};
            #pragma unroll
            for (int i = 0; i < 4; i++) {
                int d = ch * 4 + i;
                Kt[swzoff(d, r >> 2) + (r & 3)] = ka[i];
            }
            *(float4*)(&Vs[r * 64 + ch * 4]) = vv;
        }
        __syncthreads();

        // ---- S = Q K^T (4x4 per thread) ----
        float s[4][4] = {};
        #pragma unroll
        for (int d = 0; d < 64; d++) {
            float4 a4 = *(const float4*)(&Qt[swzoff(d, ty)]);  // broadcast per ty
            float4 b4 = *(const float4*)(&Kt[swzoff(d, tx)]);  // 16 distinct groups
            float ar[4] = {a4.x, a4.y, a4.z, a4.w};
            float br[4] = {b4.x, b4.y, b4.z, b4.w};
            #pragma unroll
            for (int i = 0; i < 4; i++)
                #pragma unroll
                for (int j = 0; j < 4; j++)
                    s[i][j] = fmaf(ar[i], br[j], s[i][j]);
        }

        // ---- online softmax (row state replicated across the 16 tx threads) ----
        const float scale = 0.125f;   // 1/sqrt(64)
        #pragma unroll
        for (int i = 0; i < 4; i++) {
            float rm = -1e30f;
            #pragma unroll
            for (int j = 0; j < 4; j++) {
                s[i][j] *= scale;
                rm = fmaxf(rm, s[i][j]);
            }
            rm = fmaxf(rm, __shfl_xor_sync(0xffffffffu, rm, 1));
            rm = fmaxf(rm, __shfl_xor_sync(0xffffffffu, rm, 2));
            rm = fmaxf(rm, __shfl_xor_sync(0xffffffffu, rm, 4));
            rm = fmaxf(rm, __shfl_xor_sync(0xffffffffu, rm, 8));

            float mnew = fmaxf(m[i], rm);
            float alpha = __expf(m[i] - mnew);
            float rs = 0.f;
            #pragma unroll
            for (int j = 0; j < 4; j++) {
                s[i][j] = __expf(s[i][j] - mnew);   // s becomes P
                rs += s[i][j];
            }
            rs += __shfl_xor_sync(0xffffffffu, rs, 1);
            rs += __shfl_xor_sync(0xffffffffu, rs, 2);
            rs += __shfl_xor_sync(0xffffffffu, rs, 4);
            rs += __shfl_xor_sync(0xffffffffu, rs, 8);

            l[i] = l[i] * alpha + rs;
            m[i] = mnew;
            #pragma unroll
            for (int j = 0; j < 4; j++) o[i][j] *= alpha;
        }

        __syncthreads();   // everyone done reading Kt before we overwrite it with P^T

        // ---- write P^T into Kt's space: Pt[key k][query r], swizzled ----
        #pragma unroll
        for (int j = 0; j < 4; j++) {
            int kk = tx * 4 + j;
            float4 pv = make_float4(s[0][j], s[1][j], s[2][j], s[3][j]);
            *(float4*)(&Kt[swzoff(kk, ty)]) = pv;
        }
        __syncthreads();

        // ---- O += P V  (4x4 per thread: rows 4ty.., d cols 4tx..) ----
        #pragma unroll
        for (int k = 0; k < 64; k++) {
            float4 a4 = *(const float4*)(&Kt[swzoff(k, ty)]);   // P rows (broadcast per ty)
            float4 v4 = *(const float4*)(&Vs[k * 64 + tx * 4]); // V cols
            float ar[4] = {a4.x, a4.y, a4.z, a4.w};
            float vr[4] = {v4.x, v4.y, v4.z, v4.w};
            #pragma unroll
            for (int i = 0; i < 4; i++)
                #pragma unroll
                for (int j = 0; j < 4; j++)
                    o[i][j] = fmaf(ar[i], vr[j], o[i][j]);
        }
    }

    // ---- normalize and store to [B,T,C] layout ----
    #pragma unroll
    for (int i = 0; i < 4; i++) {
        float inv = 1.0f / l[i];
        float4 r;
        r.x = o[i][0] * inv;
        r.y = o[i][1] * inv;
        r.z = o[i][2] * inv;
        r.w = o[i][3] * inv;
        *(float4*)(out + (size_t)(bT + q0 + ty * 4 + i) * D_MODEL + hoff + tx * 4) = r;
    }
}

// ---------------------------------------------------------------------------
// Launch: qkv = x @ W_qkv + b_qkv ; flash-attn ; out = attn @ W_out + b_out
// ---------------------------------------------------------------------------
extern "C" void kernel_launch(void* const* d_in, const int* in_sizes, int n_in,
                              void* d_out, int out_size)
{
    (void)in_sizes; (void)n_in; (void)out_size;
    const float* x    = (const float*)d_in[0];
    const float* Wqkv = (const float*)d_in[1];
    const float* bqkv = (const float*)d_in[2];
    const float* Wout = (const float*)d_in[3];
    const float* bout = (const float*)d_in[4];
    float* out = (float*)d_out;

    float *qkv = nullptr, *attn = nullptr;
    cudaGetSymbolAddress((void**)&qkv,  g_qkv);
    cudaGetSymbolAddress((void**)&attn, g_attn);

    dim3 blk(256);

    // GEMM1: [4096,1024] @ [1024,3072] + b
    sgemm_bias<<<dim3((3 * D_MODEL) / 64, M_TOT / 64), blk>>>(
        x, Wqkv, bqkv, qkv, M_TOT, 3 * D_MODEL, D_MODEL);

    // Attention: grid (q-tiles, heads, batch)
    attn_kernel<<<dim3(SEQ / 64, NH, BATCH), blk>>>(qkv, attn);

    // GEMM2: [4096,1024] @ [1024,1024] + b
    sgemm_bias<<<dim3(D_MODEL / 64, M_TOT / 64), blk>>>(
        attn, Wout, bout, out, M_TOT, D_MODEL, D_MODEL);
}